// round 6
// baseline (speedup 1.0000x reference)
#include <cuda_runtime.h>
#include <math.h>

#define BB 4096
#define DIM 2048
#define NE 8
#define NH 16
#define HD 128
#define N3 (3*DIM)
#define N2 (2*DIM)
#define BM 128
#define BN 128
#define BK 8
#define SLOT_CAP (2*BB + NE*BM)      // 9216
#define SLOT_TILES (SLOT_CAP/BM)     // 72
#define SCALE_F 0.08838834764831845f // 128^-0.5

// ---------------- scratch (device globals; referenced ONLY in device code) ---
// CRITICAL: never pass these as host-side kernel arguments. nvcc's host shadow
// symbol gives a HOST address, and GB300's ATS dereferences it silently
// (reads zeros / writes lost) instead of faulting. Root cause of rounds 1-5.
__device__ float g_q   [(size_t)BB*DIM];    // qkv_y[:,0]  (q)
__device__ float g_kv  [(size_t)BB*N2];     // qkv_x[:,1:3] (k then v)
__device__ float g_attn[(size_t)BB*DIM];    // attention out, (d*NH+h) flatten
__device__ int   g_slot_tok[SLOT_CAP];
__device__ float g_slot_w  [SLOT_CAP];
__device__ int   g_cnt [NE];
__device__ int   g_off [NE+1];
__device__ int   g_fill[NE];
__device__ int   g_e0[BB], g_e1[BB];
__device__ float g_w0[BB], g_w1[BB];

// ---------------- zero / init (required every call: graph replays) ----------
__global__ void k_zero() {
    int i = blockIdx.x * blockDim.x + threadIdx.x;
    int stride = gridDim.x * blockDim.x;
    for (int j = i; j < BB*DIM;  j += stride) g_q[j]  = 0.f;
    for (int j = i; j < BB*N2;   j += stride) g_kv[j] = 0.f;
    for (int j = i; j < SLOT_CAP; j += stride) g_slot_tok[j] = -1;
    if (i < NE) { g_cnt[i] = 0; g_fill[i] = 0; }
}

// ---------------- gating: one warp per token ----------------
__global__ void k_gate(const float* __restrict__ x,
                       const float* __restrict__ Wg,
                       const float* __restrict__ bg) {
    int warp = (blockIdx.x * blockDim.x + threadIdx.x) >> 5;
    int lane = threadIdx.x & 31;
    if (warp >= BB) return;
    const float* xr = x + (size_t)warp * DIM;
    float acc[NE];
#pragma unroll
    for (int e = 0; e < NE; e++) acc[e] = 0.f;
    for (int d = lane; d < DIM; d += 32) {
        float xv = xr[d];
        const float4* w4 = reinterpret_cast<const float4*>(Wg + (size_t)d * NE);
        float4 a = w4[0], b = w4[1];
        acc[0] += xv * a.x; acc[1] += xv * a.y; acc[2] += xv * a.z; acc[3] += xv * a.w;
        acc[4] += xv * b.x; acc[5] += xv * b.y; acc[6] += xv * b.z; acc[7] += xv * b.w;
    }
#pragma unroll
    for (int e = 0; e < NE; e++) {
#pragma unroll
        for (int o = 16; o > 0; o >>= 1) acc[e] += __shfl_down_sync(0xffffffffu, acc[e], o);
    }
    if (lane == 0) {
        float z[NE], p[NE];
        float m = -1e30f;
#pragma unroll
        for (int e = 0; e < NE; e++) { z[e] = acc[e] + bg[e]; m = fmaxf(m, z[e]); }
        float s = 0.f;
#pragma unroll
        for (int e = 0; e < NE; e++) { p[e] = expf(z[e] - m); s += p[e]; }
        float inv = 1.f / s;
        int e0 = 0; float v0 = p[0];
#pragma unroll
        for (int e = 1; e < NE; e++) if (p[e] > v0) { v0 = p[e]; e0 = e; }
        int e1 = (e0 == 0) ? 1 : 0; float v1 = p[e1];
#pragma unroll
        for (int e = 0; e < NE; e++) if (e != e0 && p[e] > v1) { v1 = p[e]; e1 = e; }
        g_e0[warp] = e0; g_w0[warp] = v0 * inv;
        g_e1[warp] = e1; g_w1[warp] = v1 * inv;
        atomicAdd(&g_cnt[e0], 1);
        atomicAdd(&g_cnt[e1], 1);
    }
}

// ---------------- aligned bucket offsets ----------------
__global__ void k_offsets() {
    int o = 0;
    for (int e = 0; e < NE; e++) {
        g_off[e] = o;
        o += (g_cnt[e] + BM - 1) & ~(BM - 1);
    }
    g_off[NE] = o;
}

// ---------------- scatter (token, weight) into expert buckets ----------------
__global__ void k_scatter() {
    int b = blockIdx.x * blockDim.x + threadIdx.x;
    if (b >= BB) return;
    int e0 = g_e0[b];
    int p0 = atomicAdd(&g_fill[e0], 1);
    g_slot_tok[g_off[e0] + p0] = b;
    g_slot_w  [g_off[e0] + p0] = g_w0[b];
    int e1 = g_e1[b];
    int p1 = atomicAdd(&g_fill[e1], 1);
    g_slot_tok[g_off[e1] + p1] = b;
    g_slot_w  [g_off[e1] + p1] = g_w1[b];
}

// ---------------- routed expert GEMM ----------------
// which==0: A=x, W cols [DIM,3*DIM) -> scatter-add into g_kv (ldc=N2)
// which==1: A=y, W cols [0,DIM)     -> scatter-add into g_q  (ldc=DIM)
// Output buffers selected in DEVICE code (see note at globals).
__global__ void __launch_bounds__(256, 2)
k_moe_gemm(const float* __restrict__ Asrc, const float* __restrict__ W,
           int which) {
    __shared__ float As[BK][BM];
    __shared__ float Bs[BK][BN];
    int row0 = blockIdx.x * BM;
    if (row0 >= g_off[NE]) return;
    float* C   = which ? g_q : g_kv;
    int   ldc  = which ? DIM : N2;
    int colOff = which ? 0   : DIM;
    int e = 0;
    while (e < NE - 1 && row0 >= g_off[e + 1]) e++;
    int col0 = blockIdx.y * BN;
    const float* We = W + (size_t)e * DIM * N3 + colOff + col0;
    int tid = threadIdx.x;
    int aRow = tid >> 1;
    int aCol = (tid & 1) * 4;
    int tokA = g_slot_tok[row0 + aRow];
    int bRow = tid >> 5;
    int bCol = (tid & 31) * 4;
    int ty = tid >> 4, tx = tid & 15;
    int ty8 = ty * 8, tx8 = tx * 8;
    float acc[8][8];
#pragma unroll
    for (int i = 0; i < 8; i++)
#pragma unroll
        for (int j = 0; j < 8; j++) acc[i][j] = 0.f;

    const float* aPtr = (tokA >= 0) ? (Asrc + (size_t)tokA * DIM + aCol) : nullptr;

    for (int k0 = 0; k0 < DIM; k0 += BK) {
        float4 av = aPtr ? *(const float4*)(aPtr + k0) : make_float4(0.f, 0.f, 0.f, 0.f);
        As[aCol + 0][aRow] = av.x;
        As[aCol + 1][aRow] = av.y;
        As[aCol + 2][aRow] = av.z;
        As[aCol + 3][aRow] = av.w;
        float4 bv = *(const float4*)(We + (size_t)(k0 + bRow) * N3 + bCol);
        *(float4*)&Bs[bRow][bCol] = bv;
        __syncthreads();
#pragma unroll
        for (int kk = 0; kk < BK; kk++) {
            float4 a0 = *(const float4*)&As[kk][ty8];
            float4 a1 = *(const float4*)&As[kk][ty8 + 4];
            float4 b0 = *(const float4*)&Bs[kk][tx8];
            float4 b1 = *(const float4*)&Bs[kk][tx8 + 4];
            float af[8] = {a0.x, a0.y, a0.z, a0.w, a1.x, a1.y, a1.z, a1.w};
            float bf[8] = {b0.x, b0.y, b0.z, b0.w, b1.x, b1.y, b1.z, b1.w};
#pragma unroll
            for (int i = 0; i < 8; i++)
#pragma unroll
                for (int j = 0; j < 8; j++) acc[i][j] += af[i] * bf[j];
        }
        __syncthreads();
    }
    // epilogue: scaled scatter-add per token (each token lives in exactly 2 buckets)
#pragma unroll
    for (int i = 0; i < 8; i++) {
        int r = row0 + ty8 + i;
        int tok = g_slot_tok[r];
        if (tok < 0) continue;
        float w = g_slot_w[r];
        float* crow = C + (size_t)tok * ldc + col0 + tx8;
#pragma unroll
        for (int j = 0; j < 8; j++) atomicAdd(&crow[j], w * acc[i][j]);
    }
}

// ---------------- per-token 16x16 head-attention ----------------
__global__ void k_attn() {
    int b = blockIdx.x;
    __shared__ float sQ[DIM], sK[DIM], sV[DIM];
    __shared__ float sS[NH][NH + 1];
    int tid = threadIdx.x;
    const float* qb = g_q  + (size_t)b * DIM;
    const float* kb = g_kv + (size_t)b * N2;
    const float* vb = kb + DIM;
    for (int i = tid; i < DIM; i += 256) { sQ[i] = qb[i]; sK[i] = kb[i]; sV[i] = vb[i]; }
    __syncthreads();
    {
        int h = tid >> 4, g = tid & 15;
        float s = 0.f;
        int qb0 = h * HD, kb0 = g * HD;
#pragma unroll 8
        for (int dd = 0; dd < HD; dd++) {
            int d = (dd + tid) & (HD - 1);   // skew avoids bank conflicts
            s += sQ[qb0 + d] * sK[kb0 + d];
        }
        sS[h][g] = s * SCALE_F;
    }
    __syncthreads();
    if (tid < NH) {
        float m = -1e30f;
#pragma unroll
        for (int g = 0; g < NH; g++) m = fmaxf(m, sS[tid][g]);
        float sum = 0.f;
#pragma unroll
        for (int g = 0; g < NH; g++) { float p = expf(sS[tid][g] - m); sS[tid][g] = p; sum += p; }
        float inv = 1.f / sum;
#pragma unroll
        for (int g = 0; g < NH; g++) sS[tid][g] *= inv;
    }
    __syncthreads();
    float* ob = g_attn + (size_t)b * DIM;
    for (int i = tid; i < DIM; i += 256) {
        int h = i >> 7, d = i & (HD - 1);
        float o = 0.f;
#pragma unroll
        for (int g = 0; g < NH; g++) o += sS[h][g] * sV[g * HD + d];
        ob[d * NH + h] = o;   // swapaxes(1,2) flatten: index = d*H + h
    }
}

// ---------------- output projection: out = g_attn @ Wp + bp ----------------
__global__ void __launch_bounds__(256, 2)
k_proj(const float* __restrict__ Wp, const float* __restrict__ bp,
       float* __restrict__ Cout) {
    __shared__ float As[BK][BM];
    __shared__ float Bs[BK][BN];
    int row0 = blockIdx.x * BM;
    int col0 = blockIdx.y * BN;
    int tid = threadIdx.x;
    int aRow = tid >> 1;
    int aCol = (tid & 1) * 4;
    int bRow = tid >> 5;
    int bCol = (tid & 31) * 4;
    int ty = tid >> 4, tx = tid & 15;
    int ty8 = ty * 8, tx8 = tx * 8;
    float acc[8][8];
#pragma unroll
    for (int i = 0; i < 8; i++)
#pragma unroll
        for (int j = 0; j < 8; j++) acc[i][j] = 0.f;
    const float* aPtr = g_attn + (size_t)(row0 + aRow) * DIM + aCol;
    const float* wPtr = Wp + col0;
    for (int k0 = 0; k0 < DIM; k0 += BK) {
        float4 av = *(const float4*)(aPtr + k0);
        As[aCol + 0][aRow] = av.x;
        As[aCol + 1][aRow] = av.y;
        As[aCol + 2][aRow] = av.z;
        As[aCol + 3][aRow] = av.w;
        float4 bv = *(const float4*)(wPtr + (size_t)(k0 + bRow) * DIM + bCol);
        *(float4*)&Bs[bRow][bCol] = bv;
        __syncthreads();
#pragma unroll
        for (int kk = 0; kk < BK; kk++) {
            float4 a0 = *(const float4*)&As[kk][ty8];
            float4 a1 = *(const float4*)&As[kk][ty8 + 4];
            float4 b0 = *(const float4*)&Bs[kk][tx8];
            float4 b1 = *(const float4*)&Bs[kk][tx8 + 4];
            float af[8] = {a0.x, a0.y, a0.z, a0.w, a1.x, a1.y, a1.z, a1.w};
            float bf[8] = {b0.x, b0.y, b0.z, b0.w, b1.x, b1.y, b1.z, b1.w};
#pragma unroll
            for (int i = 0; i < 8; i++)
#pragma unroll
                for (int j = 0; j < 8; j++) acc[i][j] += af[i] * bf[j];
        }
        __syncthreads();
    }
#pragma unroll
    for (int i = 0; i < 8; i++) {
        float* crow = Cout + (size_t)(row0 + ty8 + i) * DIM + col0 + tx8;
#pragma unroll
        for (int j = 0; j < 8; j++) crow[j] = bp[col0 + tx8 + j] + acc[i][j];
    }
}

// ---------------- launch ----------------
extern "C" void kernel_launch(void* const* d_in, const int* in_sizes, int n_in,
                              void* d_out, int out_size) {
    // Identify inputs by unique element counts (robust to metadata ordering).
    const float *x = nullptr, *y = nullptr, *We = nullptr, *Wg = nullptr;
    const float *bg = nullptr, *Wp = nullptr, *bp = nullptr;
    for (int i = 0; i < n_in; i++) {
        const float* p = (const float*)d_in[i];
        switch (in_sizes[i]) {
            case 100663296: We = p; break;                    // 8*2048*6144
            case 8388608:   if (!x) x = p; else y = p; break; // 4096*2048
            case 4194304:   Wp = p; break;                    // 2048*2048
            case 16384:     Wg = p; break;                    // 2048*8
            case 2048:      bp = p; break;
            case 8:         bg = p; break;
            default: break;
        }
    }
    float* out = (float*)d_out;

    k_zero<<<2048, 256>>>();
    k_gate<<<BB / 8, 256>>>(x, Wg, bg);
    k_offsets<<<1, 1>>>();
    k_scatter<<<BB / 256, 256>>>();
    {   // x-path: k,v  -> g_kv
        dim3 grid(SLOT_TILES, N2 / BN);
        k_moe_gemm<<<grid, 256>>>(x, We, 0);
    }
    {   // y-path: q -> g_q
        dim3 grid(SLOT_TILES, DIM / BN);
        k_moe_gemm<<<grid, 256>>>(y, We, 1);
    }
    k_attn<<<BB, 256>>>();
    {
        dim3 grid(BB / BM, DIM / BN);
        k_proj<<<grid, 256>>>(Wp, bp, out);
    }
}

// round 8
// speedup vs baseline: 2.0698x; 2.0698x over previous
#include <cuda_runtime.h>
#include <cuda_bf16.h>
#include <math.h>
#include <stdint.h>

#define BB 4096
#define DIM 2048
#define NE 8
#define NH 16
#define HD 128
#define N3 6144
#define N2 4096
#define SLOT_CAP 9216
#define SLOT_TILES 72
#define SCALE_F 0.08838834764831845f

// ---- tile config ----
#define TM 128
#define TN 128
#define KC 64                 // K per chunk
#define NCHUNK (DIM/KC)       // 32
// tcgen05 kind::f16 idesc: bf16 in, f32 acc, M=128, N=128
#define IDESC 0x08200490u

// ---- dynamic smem layout (bytes) ----
#define OFF_TMEM  0
#define OFF_MBAR  16
#define OFF_STOK  64
#define OFF_STAGE 1024
#define STAGE_LD  132          // padded floats per stage row
#define OFF_BUF   34816        // 1024-aligned; 2 bufs x 4 tiles x 16KB
#define TILE_B    16384
#define SMEM_TOTAL (OFF_BUF + 2*4*TILE_B)   // 165888

// Arch-specific (sm_103a/100a) pass gets tcgen05; generic pass gets mma.sync.
#if defined(__CUDA_ARCH_FEAT_SM103_ALL) || defined(__CUDA_ARCH_FEAT_SM100_ALL) || defined(__CUDA_ARCH_FEAT_SM101_ALL)
#define USE_TCGEN05 1
#else
#define USE_TCGEN05 0
#endif

// ---------------- scratch (device globals; DEVICE-CODE ONLY — ATS trap!) ----
__device__ float g_qs  [(size_t)SLOT_CAP*DIM];  // per-slot q
__device__ float g_kvs [(size_t)SLOT_CAP*N2];   // per-slot k|v
__device__ float g_attn[(size_t)BB*DIM];        // attn out, (d*NH+h) flatten
__device__ int   g_slot_tok[SLOT_CAP];
__device__ int   g_cnt[NE], g_off[NE+1], g_fill[NE];
__device__ int   g_e0[BB], g_e1[BB];
__device__ float g_w0[BB], g_w1[BB];
__device__ int   g_s0[BB], g_s1[BB];

// ---------------- helpers ----------------
#define SWZ(o) ((o) ^ (((o) >> 3) & 0x70))

__device__ __forceinline__ void split4(float4 v, uint2& hi, uint2& lo) {
    __nv_bfloat16 h0 = __float2bfloat16_rn(v.x), h1 = __float2bfloat16_rn(v.y);
    __nv_bfloat16 h2 = __float2bfloat16_rn(v.z), h3 = __float2bfloat16_rn(v.w);
    float r0 = v.x - __bfloat162float(h0), r1 = v.y - __bfloat162float(h1);
    float r2 = v.z - __bfloat162float(h2), r3 = v.w - __bfloat162float(h3);
    __nv_bfloat16 l0 = __float2bfloat16_rn(r0), l1 = __float2bfloat16_rn(r1);
    __nv_bfloat16 l2 = __float2bfloat16_rn(r2), l3 = __float2bfloat16_rn(r3);
    hi.x = ((uint32_t)*(uint16_t*)&h1 << 16) | *(uint16_t*)&h0;
    hi.y = ((uint32_t)*(uint16_t*)&h3 << 16) | *(uint16_t*)&h2;
    lo.x = ((uint32_t)*(uint16_t*)&l1 << 16) | *(uint16_t*)&l0;
    lo.y = ((uint32_t)*(uint16_t*)&l3 << 16) | *(uint16_t*)&l2;
}

#if USE_TCGEN05
__device__ __forceinline__ uint32_t s2u(const void* p) {
    uint32_t a;
    asm("{ .reg .u64 t; cvta.to.shared.u64 t, %1; cvt.u32.u64 %0, t; }"
        : "=r"(a) : "l"(p));
    return a;
}
__device__ __forceinline__ uint32_t elect1() {
    uint32_t p;
    asm volatile("{ .reg .pred p; elect.sync _|p, 0xFFFFFFFF; selp.b32 %0, 1, 0, p; }"
                 : "=r"(p));
    return p;
}
__device__ __forceinline__ uint64_t mkdesc(uint32_t a) {
    return (2ULL << 61) | (1ULL << 46) | (64ULL << 32) | (1ULL << 16)
         | ((uint64_t)(a >> 4) & 0x3FFF);
}
__device__ __forceinline__ void mma_ss(uint32_t d, uint64_t a, uint64_t b, uint32_t en) {
    asm volatile(
        "{\n\t.reg .pred p;\n\tsetp.ne.u32 p, %4, 0;\n\t"
        "tcgen05.mma.cta_group::1.kind::f16 [%0], %1, %2, %3, {%5, %5, %5, %5}, p;\n\t}"
        :: "r"(d), "l"(a), "l"(b), "r"(IDESC), "r"(en), "r"(0u) : "memory");
}
__device__ __forceinline__ void mwait(uint32_t mbar, uint32_t parity) {
    uint32_t done;
    asm volatile(
        "{\n\t.reg .pred p;\n\t"
        "mbarrier.try_wait.parity.acquire.cta.shared::cta.b64 p, [%1], %2;\n\t"
        "selp.b32 %0, 1, 0, p;\n\t}"
        : "=r"(done) : "r"(mbar), "r"(parity) : "memory");
    if (!done) {
        asm volatile(
            "{\n\t.reg .pred P1;\n\t"
            "W1_%=:\n\t"
            "mbarrier.try_wait.parity.acquire.cta.shared::cta.b64 P1, [%0], %1, 0x989680;\n\t"
            "@P1 bra.uni W2_%=;\n\t"
            "bra.uni W1_%=;\n\t"
            "W2_%=:\n\t}"
            :: "r"(mbar), "r"(parity) : "memory");
    }
}
#define LDTM32(r, a) \
    asm volatile( \
        "tcgen05.ld.sync.aligned.32x32b.x32.b32 " \
        "{%0, %1, %2, %3, %4, %5, %6, %7, " \
        " %8, %9, %10, %11, %12, %13, %14, %15, " \
        " %16, %17, %18, %19, %20, %21, %22, %23, " \
        " %24, %25, %26, %27, %28, %29, %30, %31}, [%32];" \
        : "=r"((r)[0]),  "=r"((r)[1]),  "=r"((r)[2]),  "=r"((r)[3]), \
          "=r"((r)[4]),  "=r"((r)[5]),  "=r"((r)[6]),  "=r"((r)[7]), \
          "=r"((r)[8]),  "=r"((r)[9]),  "=r"((r)[10]), "=r"((r)[11]), \
          "=r"((r)[12]), "=r"((r)[13]), "=r"((r)[14]), "=r"((r)[15]), \
          "=r"((r)[16]), "=r"((r)[17]), "=r"((r)[18]), "=r"((r)[19]), \
          "=r"((r)[20]), "=r"((r)[21]), "=r"((r)[22]), "=r"((r)[23]), \
          "=r"((r)[24]), "=r"((r)[25]), "=r"((r)[26]), "=r"((r)[27]), \
          "=r"((r)[28]), "=r"((r)[29]), "=r"((r)[30]), "=r"((r)[31]) \
        : "r"(a))
#else
// legacy tensor-core path (compiles on generic compute_103)
__device__ __forceinline__ void mma16816(float* c, const uint32_t* a, const uint32_t* b) {
    asm volatile(
        "mma.sync.aligned.m16n8k16.row.col.f32.bf16.bf16.f32 "
        "{%0,%1,%2,%3}, {%4,%5,%6,%7}, {%8,%9}, {%0,%1,%2,%3};"
        : "+f"(c[0]), "+f"(c[1]), "+f"(c[2]), "+f"(c[3])
        : "r"(a[0]), "r"(a[1]), "r"(a[2]), "r"(a[3]), "r"(b[0]), "r"(b[1]));
}
#endif

// ---------------- small setup kernels ----------------
__global__ void k_init() {
    int i = blockIdx.x * 256 + threadIdx.x;
    if (i < SLOT_CAP) g_slot_tok[i] = -1;
    if (i < NE) { g_cnt[i] = 0; g_fill[i] = 0; }
}

__global__ void k_gate(const float* __restrict__ x,
                       const float* __restrict__ Wg,
                       const float* __restrict__ bg) {
    int warp = (blockIdx.x * blockDim.x + threadIdx.x) >> 5;
    int lane = threadIdx.x & 31;
    if (warp >= BB) return;
    const float* xr = x + (size_t)warp * DIM;
    float acc[NE];
#pragma unroll
    for (int e = 0; e < NE; e++) acc[e] = 0.f;
    for (int d = lane; d < DIM; d += 32) {
        float xv = xr[d];
        const float4* w4 = reinterpret_cast<const float4*>(Wg + (size_t)d * NE);
        float4 a = w4[0], b = w4[1];
        acc[0] += xv * a.x; acc[1] += xv * a.y; acc[2] += xv * a.z; acc[3] += xv * a.w;
        acc[4] += xv * b.x; acc[5] += xv * b.y; acc[6] += xv * b.z; acc[7] += xv * b.w;
    }
#pragma unroll
    for (int e = 0; e < NE; e++) {
#pragma unroll
        for (int o = 16; o > 0; o >>= 1) acc[e] += __shfl_down_sync(0xffffffffu, acc[e], o);
    }
    if (lane == 0) {
        float z[NE], p[NE];
        float m = -1e30f;
#pragma unroll
        for (int e = 0; e < NE; e++) { z[e] = acc[e] + bg[e]; m = fmaxf(m, z[e]); }
        float s = 0.f;
#pragma unroll
        for (int e = 0; e < NE; e++) { p[e] = expf(z[e] - m); s += p[e]; }
        float inv = 1.f / s;
        int e0 = 0; float v0 = p[0];
#pragma unroll
        for (int e = 1; e < NE; e++) if (p[e] > v0) { v0 = p[e]; e0 = e; }
        int e1 = (e0 == 0) ? 1 : 0; float v1 = p[e1];
#pragma unroll
        for (int e = 0; e < NE; e++) if (e != e0 && p[e] > v1) { v1 = p[e]; e1 = e; }
        g_e0[warp] = e0; g_w0[warp] = v0 * inv;
        g_e1[warp] = e1; g_w1[warp] = v1 * inv;
        atomicAdd(&g_cnt[e0], 1);
        atomicAdd(&g_cnt[e1], 1);
    }
}

__global__ void k_offsets() {
    int o = 0;
    for (int e = 0; e < NE; e++) {
        g_off[e] = o;
        o += (g_cnt[e] + TM - 1) & ~(TM - 1);
    }
    g_off[NE] = o;
}

__global__ void k_scatter() {
    int b = blockIdx.x * blockDim.x + threadIdx.x;
    if (b >= BB) return;
    int e0 = g_e0[b];
    int s0 = g_off[e0] + atomicAdd(&g_fill[e0], 1);
    g_slot_tok[s0] = b;  g_s0[b] = s0;
    int e1 = g_e1[b];
    int s1 = g_off[e1] + atomicAdd(&g_fill[e1], 1);
    g_slot_tok[s1] = b;  g_s1[b] = s1;
}

// ---------------- GEMM: 128x128 tile, f32 via 3x bf16 split ----------------
// mode 0: A = x[slot gather], B = We[e] cols [DIM,3*DIM) -> g_kvs (ld 4096)
// mode 1: A = y[slot gather], B = We[e] cols [0,DIM)     -> g_qs  (ld 2048)
// mode 2: A = g_attn (dense),  B = Wp                    -> dout + bp
__global__ __launch_bounds__(256, 1)
void tc_gemm(const float* __restrict__ x, const float* __restrict__ y,
             const float* __restrict__ We, const float* __restrict__ Wp,
             const float* __restrict__ bp, float* __restrict__ dout, int mode)
{
    extern __shared__ char sm[];
    const int tid = threadIdx.x, wid = tid >> 5, lane = tid & 31;
    const int row0 = blockIdx.x * TM, col0 = blockIdx.y * TN;

    const float* Asrc; const float* Bsrc; long ldb; bool gather;
    if (mode == 2) {
        Asrc = g_attn; Bsrc = Wp + col0; ldb = DIM; gather = false;
    } else {
        if (row0 >= g_off[NE]) return;
        int e = 0;
        while (e < NE - 1 && row0 >= g_off[e + 1]) e++;
        if (mode == 0) { Asrc = x; Bsrc = We + (size_t)e * DIM * N3 + DIM + col0; }
        else           { Asrc = y; Bsrc = We + (size_t)e * DIM * N3 + col0; }
        ldb = N3; gather = true;
    }

    int* sTok = (int*)(sm + OFF_STOK);
    if (tid < TM) sTok[tid] = gather ? g_slot_tok[row0 + tid] : (row0 + tid);
    float* stage = (float*)(sm + OFF_STAGE);

#if USE_TCGEN05
    uint32_t sb = s2u(sm);
    if (wid == 0) {
        asm volatile("tcgen05.alloc.cta_group::1.sync.aligned.shared::cta.b32 [%0], %1;"
                     :: "r"(sb + OFF_TMEM), "r"(128u) : "memory");
    }
    if (tid == 0) {
        asm volatile("mbarrier.init.shared.b64 [%0], 1;" :: "r"(sb + OFF_MBAR) : "memory");
        asm volatile("mbarrier.init.shared.b64 [%0], 1;" :: "r"(sb + OFF_MBAR + 8) : "memory");
    }
    __syncthreads();
    uint32_t tmem;
    asm volatile("ld.shared.b32 %0, [%1];" : "=r"(tmem) : "r"(sb + OFF_TMEM));

    const int ar = tid >> 1, ah = tid & 1;
    const int atok = sTok[ar];
    const float* aRow = (atok >= 0) ? (Asrc + (size_t)atok * DIM + 32 * ah) : nullptr;
    const int bn = tid >> 1, bh = (tid & 1) * 32;

    int ph0 = 0, ph1 = 0;
    for (int c = 0; c < NCHUNK; c++) {
        const int buf = c & 1;
        const uint32_t base = OFF_BUF + buf * (4 * TILE_B);
        char* pAh = sm + base;
        char* pAl = sm + base + TILE_B;
        char* pBh = sm + base + 2 * TILE_B;
        char* pBl = sm + base + 3 * TILE_B;
        if (c >= 2) {
            if (buf == 0) { mwait(sb + OFF_MBAR, ph0); ph0 ^= 1; }
            else          { mwait(sb + OFF_MBAR + 8, ph1); ph1 ^= 1; }
        }
        const int k0 = c * KC;
        {   // stage W tile [KC][TN] f32
            const float* wp = Bsrc + (size_t)(k0 + 8 * wid) * ldb + 4 * lane;
#pragma unroll
            for (int p = 0; p < 8; p++) {
                float4 v = *(const float4*)(wp + (size_t)p * ldb);
                float* d = stage + (8 * wid + p) * STAGE_LD + 4 * lane;
                d[0] = v.x; d[1] = v.y; d[2] = v.z; d[3] = v.w;
            }
        }
        __syncthreads();
        {   // convert B (transpose)
#pragma unroll
            for (int g = 0; g < 8; g++) {
                int k4 = bh + 4 * g;
                float4 f;
                f.x = stage[(k4 + 0) * STAGE_LD + bn];
                f.y = stage[(k4 + 1) * STAGE_LD + bn];
                f.z = stage[(k4 + 2) * STAGE_LD + bn];
                f.w = stage[(k4 + 3) * STAGE_LD + bn];
                uint2 hi, lo;
                split4(f, hi, lo);
                uint32_t off = SWZ((uint32_t)(bn * 128 + 2 * k4));
                *(uint2*)(pBh + off) = hi;
                *(uint2*)(pBl + off) = lo;
            }
        }
        {   // convert A
#pragma unroll
            for (int i = 0; i < 8; i++) {
                float4 v = aRow ? *(const float4*)(aRow + k0 + 4 * i)
                                : make_float4(0.f, 0.f, 0.f, 0.f);
                uint2 hi, lo;
                split4(v, hi, lo);
                uint32_t off = SWZ((uint32_t)(ar * 128 + 64 * ah + 8 * i));
                *(uint2*)(pAh + off) = hi;
                *(uint2*)(pAl + off) = lo;
            }
        }
        asm volatile("fence.proxy.async.shared::cta;" ::: "memory");
        __syncthreads();
        if (wid == 0) {
            if (elect1()) {
                uint32_t a32 = sb + base;
                uint64_t dAh = mkdesc(a32);
                uint64_t dAl = mkdesc(a32 + TILE_B);
                uint64_t dBh = mkdesc(a32 + 2 * TILE_B);
                uint64_t dBl = mkdesc(a32 + 3 * TILE_B);
#pragma unroll
                for (int s = 0; s < 4; s++) {
                    uint64_t o = 2 * s;
                    mma_ss(tmem, dAh + o, dBh + o, (c > 0 || s > 0) ? 1u : 0u);
                    mma_ss(tmem, dAh + o, dBl + o, 1u);
                    mma_ss(tmem, dAl + o, dBh + o, 1u);
                }
                asm volatile(
                    "tcgen05.commit.cta_group::1.mbarrier::arrive::one.shared::cluster.b64 [%0];"
                    :: "r"(sb + OFF_MBAR + 8 * buf) : "memory");
            }
        }
    }
    float* sBias = stage;
    if (mode == 2 && tid < TN) sBias[tid] = bp[col0 + tid];
    {
        int lb = (NCHUNK - 1) & 1;
        if (lb == 0) mwait(sb + OFF_MBAR, ph0);
        else         mwait(sb + OFF_MBAR + 8, ph1);
    }
    asm volatile("tcgen05.fence::after_thread_sync;" ::: "memory");
    __syncthreads();
    if (wid < 4) {
        int r = row0 + wid * 32 + lane;
        float* cp;
        if (mode == 0)      cp = g_kvs + (size_t)r * N2 + col0;
        else if (mode == 1) cp = g_qs + (size_t)r * DIM + col0;
        else                cp = dout + (size_t)r * DIM + col0;
#pragma unroll
        for (int it = 0; it < 4; it++) {
            uint32_t d[32];
            LDTM32(d, tmem + it * 32);
            asm volatile("tcgen05.wait::ld.sync.aligned;" ::: "memory");
#pragma unroll
            for (int m = 0; m < 8; m++) {
                float4 v;
                v.x = __uint_as_float(d[4 * m + 0]);
                v.y = __uint_as_float(d[4 * m + 1]);
                v.z = __uint_as_float(d[4 * m + 2]);
                v.w = __uint_as_float(d[4 * m + 3]);
                if (mode == 2) {
                    v.x += sBias[it * 32 + 4 * m + 0];
                    v.y += sBias[it * 32 + 4 * m + 1];
                    v.z += sBias[it * 32 + 4 * m + 2];
                    v.w += sBias[it * 32 + 4 * m + 3];
                }
                *(float4*)(cp + it * 32 + 4 * m) = v;
            }
        }
    }
    __syncthreads();
    if (tid == 0) {
        asm volatile("mbarrier.inval.shared.b64 [%0];" :: "r"(sb + OFF_MBAR) : "memory");
        asm volatile("mbarrier.inval.shared.b64 [%0];" :: "r"(sb + OFF_MBAR + 8) : "memory");
    }
    __syncthreads();
    if (wid == 0) {
        asm volatile("tcgen05.dealloc.cta_group::1.sync.aligned.b32 %0, %1;"
                     :: "r"(tmem), "r"(128u));
    }
#else
    // ---------------- mma.sync.m16n8k16 bf16 fallback ----------------
    __syncthreads();
    const int ar = tid >> 1, ah = tid & 1;
    const int atok = sTok[ar];
    const float* aRow = (atok >= 0) ? (Asrc + (size_t)atok * DIM + 32 * ah) : nullptr;
    const int bn = tid >> 1, bhh = (tid & 1) * 32;

    char* pAh = sm + OFF_BUF;
    char* pAl = sm + OFF_BUF + TILE_B;
    char* pBh = sm + OFF_BUF + 2 * TILE_B;
    char* pBl = sm + OFF_BUF + 3 * TILE_B;

    const int warpRow = (wid & 1) * 64;       // 2x4 warp grid, 64x32 per warp
    const int warpCol = (wid >> 1) * 32;
    const int qrow = lane >> 2;               // fragment row/col group
    const int klane = (lane & 3) * 2;

    float acc[4][4][4];
#pragma unroll
    for (int i = 0; i < 4; i++)
#pragma unroll
        for (int j = 0; j < 4; j++)
#pragma unroll
            for (int t = 0; t < 4; t++) acc[i][j][t] = 0.f;

    for (int c = 0; c < NCHUNK; c++) {
        const int k0 = c * KC;
        {   // stage W tile [KC][TN] f32
            const float* wp = Bsrc + (size_t)(k0 + 8 * wid) * ldb + 4 * lane;
#pragma unroll
            for (int p = 0; p < 8; p++) {
                float4 v = *(const float4*)(wp + (size_t)p * ldb);
                float* d = stage + (8 * wid + p) * STAGE_LD + 4 * lane;
                d[0] = v.x; d[1] = v.y; d[2] = v.z; d[3] = v.w;
            }
        }
        __syncthreads();
        {   // convert B (transpose) into [n][k] swizzled
#pragma unroll
            for (int g = 0; g < 8; g++) {
                int k4 = bhh + 4 * g;
                float4 f;
                f.x = stage[(k4 + 0) * STAGE_LD + bn];
                f.y = stage[(k4 + 1) * STAGE_LD + bn];
                f.z = stage[(k4 + 2) * STAGE_LD + bn];
                f.w = stage[(k4 + 3) * STAGE_LD + bn];
                uint2 hi, lo;
                split4(f, hi, lo);
                uint32_t off = SWZ((uint32_t)(bn * 128 + 2 * k4));
                *(uint2*)(pBh + off) = hi;
                *(uint2*)(pBl + off) = lo;
            }
        }
        {   // convert A into [m][k] swizzled
#pragma unroll
            for (int i = 0; i < 8; i++) {
                float4 v = aRow ? *(const float4*)(aRow + k0 + 4 * i)
                                : make_float4(0.f, 0.f, 0.f, 0.f);
                uint2 hi, lo;
                split4(v, hi, lo);
                uint32_t off = SWZ((uint32_t)(ar * 128 + 64 * ah + 8 * i));
                *(uint2*)(pAh + off) = hi;
                *(uint2*)(pAl + off) = lo;
            }
        }
        __syncthreads();
        // compute: 4 k16 steps x (4x4 tiles) x 3 split terms
#pragma unroll
        for (int s = 0; s < 4; s++) {
            const uint32_t kb = (uint32_t)(2 * (16 * s + klane));
            uint32_t aH[4][4], aL[4][4], bH[4][2], bL[4][2];
#pragma unroll
            for (int i = 0; i < 4; i++) {
                uint32_t r0 = (uint32_t)((warpRow + 16 * i + qrow) * 128);
                uint32_t r8 = r0 + 8 * 128;
                aH[i][0] = *(uint32_t*)(pAh + SWZ(r0 + kb));
                aH[i][1] = *(uint32_t*)(pAh + SWZ(r8 + kb));
                aH[i][2] = *(uint32_t*)(pAh + SWZ(r0 + kb + 16));
                aH[i][3] = *(uint32_t*)(pAh + SWZ(r8 + kb + 16));
                aL[i][0] = *(uint32_t*)(pAl + SWZ(r0 + kb));
                aL[i][1] = *(uint32_t*)(pAl + SWZ(r8 + kb));
                aL[i][2] = *(uint32_t*)(pAl + SWZ(r0 + kb + 16));
                aL[i][3] = *(uint32_t*)(pAl + SWZ(r8 + kb + 16));
            }
#pragma unroll
            for (int j = 0; j < 4; j++) {
                uint32_t n0 = (uint32_t)((warpCol + 8 * j + qrow) * 128);
                bH[j][0] = *(uint32_t*)(pBh + SWZ(n0 + kb));
                bH[j][1] = *(uint32_t*)(pBh + SWZ(n0 + kb + 16));
                bL[j][0] = *(uint32_t*)(pBl + SWZ(n0 + kb));
                bL[j][1] = *(uint32_t*)(pBl + SWZ(n0 + kb + 16));
            }
#pragma unroll
            for (int i = 0; i < 4; i++)
#pragma unroll
                for (int j = 0; j < 4; j++) {
                    mma16816(acc[i][j], aH[i], bH[j]);
                    mma16816(acc[i][j], aH[i], bL[j]);
                    mma16816(acc[i][j], aL[i], bH[j]);
                }
        }
        __syncthreads();
    }
    // epilogue from registers
    {
        float* Cb;
        long ldc;
        if (mode == 0)      { Cb = g_kvs; ldc = N2; }
        else if (mode == 1) { Cb = g_qs;  ldc = DIM; }
        else                { Cb = dout;  ldc = DIM; }
#pragma unroll
        for (int i = 0; i < 4; i++) {
            int r0 = row0 + warpRow + 16 * i + qrow;
#pragma unroll
            for (int j = 0; j < 4; j++) {
                int cc = col0 + warpCol + 8 * j + klane;
                float b0 = 0.f, b1 = 0.f;
                if (mode == 2) { b0 = bp[cc]; b1 = bp[cc + 1]; }
                *(float2*)(Cb + (size_t)r0 * ldc + cc) =
                    make_float2(acc[i][j][0] + b0, acc[i][j][1] + b1);
                *(float2*)(Cb + (size_t)(r0 + 8) * ldc + cc) =
                    make_float2(acc[i][j][2] + b0, acc[i][j][3] + b1);
            }
        }
    }
#endif
}

// ---------------- per-token 16x16 head-attention (slot-gather, no atomics) ---
__global__ void k_attn() {
    int b = blockIdx.x;
    __shared__ float sQ[DIM], sK[DIM], sV[DIM];
    __shared__ float sS[NH][NH + 1];
    int tid = threadIdx.x;
    int s0 = g_s0[b], s1 = g_s1[b];
    float w0 = g_w0[b], w1 = g_w1[b];
    const float* q0 = g_qs + (size_t)s0 * DIM;
    const float* q1 = g_qs + (size_t)s1 * DIM;
    const float* kv0 = g_kvs + (size_t)s0 * N2;
    const float* kv1 = g_kvs + (size_t)s1 * N2;
    for (int i = tid; i < DIM; i += 256) {
        sQ[i] = w0 * q0[i] + w1 * q1[i];
        sK[i] = w0 * kv0[i] + w1 * kv1[i];
        sV[i] = w0 * kv0[DIM + i] + w1 * kv1[DIM + i];
    }
    __syncthreads();
    {
        int h = tid >> 4, g = tid & 15;
        float s = 0.f;
        int qb0 = h * HD, kb0 = g * HD;
#pragma unroll 8
        for (int dd = 0; dd < HD; dd++) {
            int d = (dd + tid) & (HD - 1);
            s += sQ[qb0 + d] * sK[kb0 + d];
        }
        sS[h][g] = s * SCALE_F;
    }
    __syncthreads();
    if (tid < NH) {
        float m = -1e30f;
#pragma unroll
        for (int g = 0; g < NH; g++) m = fmaxf(m, sS[tid][g]);
        float sum = 0.f;
#pragma unroll
        for (int g = 0; g < NH; g++) { float p = expf(sS[tid][g] - m); sS[tid][g] = p; sum += p; }
        float inv = 1.f / sum;
#pragma unroll
        for (int g = 0; g < NH; g++) sS[tid][g] *= inv;
    }
    __syncthreads();
    float* ob = g_attn + (size_t)b * DIM;
    for (int i = tid; i < DIM; i += 256) {
        int h = i >> 7, d = i & (HD - 1);
        float o = 0.f;
#pragma unroll
        for (int g = 0; g < NH; g++) o += sS[h][g] * sV[g * HD + d];
        ob[d * NH + h] = o;   // swapaxes(1,2) flatten: index = d*H + h
    }
}

// ---------------- launch ----------------
extern "C" void kernel_launch(void* const* d_in, const int* in_sizes, int n_in,
                              void* d_out, int out_size) {
    const float *x = nullptr, *y = nullptr, *We = nullptr, *Wg = nullptr;
    const float *bg = nullptr, *Wp = nullptr, *bp = nullptr;
    for (int i = 0; i < n_in; i++) {
        const float* p = (const float*)d_in[i];
        switch (in_sizes[i]) {
            case 100663296: We = p; break;
            case 8388608:   if (!x) x = p; else y = p; break;
            case 4194304:   Wp = p; break;
            case 16384:     Wg = p; break;
            case 2048:      bp = p; break;
            case 8:         bg = p; break;
            default: break;
        }
    }
    float* out = (float*)d_out;

    cudaFuncSetAttribute(tc_gemm, cudaFuncAttributeMaxDynamicSharedMemorySize, SMEM_TOTAL);

    k_init<<<36, 256>>>();
    k_gate<<<BB / 8, 256>>>(x, Wg, bg);
    k_offsets<<<1, 1>>>();
    k_scatter<<<16, 256>>>();
    {   // x-path: k,v -> g_kvs
        dim3 grid(SLOT_TILES, N2 / TN);
        tc_gemm<<<grid, 256, SMEM_TOTAL>>>(x, y, We, Wp, bp, out, 0);
    }
    {   // y-path: q -> g_qs
        dim3 grid(SLOT_TILES, DIM / TN);
        tc_gemm<<<grid, 256, SMEM_TOTAL>>>(x, y, We, Wp, bp, out, 1);
    }
    k_attn<<<BB, 256>>>();
    {   // proj: g_attn @ Wp + bp -> out
        dim3 grid(BB / TM, DIM / TN);
        tc_gemm<<<grid, 256, SMEM_TOTAL>>>(x, y, We, Wp, bp, out, 2);
    }
}

// round 9
// speedup vs baseline: 2.0899x; 1.0097x over previous
#include <cuda_runtime.h>
#include <cuda_bf16.h>
#include <math.h>
#include <stdint.h>

#define BB 4096
#define DIM 2048
#define NE 8
#define NH 16
#define HD 128
#define N3 6144
#define N2 4096
#define SLOT_CAP 9216
#define SLOT_TILES 72
#define SCALE_F 0.08838834764831845f

#define TM 128
#define TN 128
#define KC 64
#define NCHUNK (DIM/KC)   // 32

// smem: sTok[128] @0, tiles @1024: 2 stages x 4 tiles x 16KB
#define OFF_BUF 1024
#define TILE_B 16384
#define STAGE_B (4*TILE_B)
#define SMEM_TOTAL (OFF_BUF + 2*STAGE_B)   // 132096

#define SWZ(o) ((o) ^ (((o) >> 3) & 0x70))

// ---------------- scratch (device globals; DEVICE-CODE ONLY — ATS trap!) ----
__device__ __nv_bfloat16 g_WeTh[(size_t)NE*N3*DIM];   // We^T hi  [e][n][k]
__device__ __nv_bfloat16 g_WeTl[(size_t)NE*N3*DIM];   // We^T lo
__device__ __nv_bfloat16 g_WpTh[(size_t)DIM*DIM];     // Wp^T hi  [n][k]
__device__ __nv_bfloat16 g_WpTl[(size_t)DIM*DIM];
__device__ __nv_bfloat16 g_xh[(size_t)BB*DIM], g_xl[(size_t)BB*DIM];
__device__ __nv_bfloat16 g_yh[(size_t)BB*DIM], g_yl[(size_t)BB*DIM];
__device__ __nv_bfloat16 g_ah[(size_t)BB*DIM], g_al[(size_t)BB*DIM];
__device__ float g_qs [(size_t)SLOT_CAP*DIM];
__device__ float g_kvs[(size_t)SLOT_CAP*N2];
__device__ int   g_slot_tok[SLOT_CAP];
__device__ int   g_cnt[NE], g_off[NE+1], g_fill[NE];
__device__ int   g_e0[BB], g_e1[BB];
__device__ float g_w0[BB], g_w1[BB];
__device__ int   g_s0[BB], g_s1[BB];

// ---------------- helpers ----------------
__device__ __forceinline__ uint32_t s2u(const void* p) {
    uint32_t a;
    asm("{ .reg .u64 t; cvta.to.shared.u64 t, %1; cvt.u32.u64 %0, t; }"
        : "=r"(a) : "l"(p));
    return a;
}
__device__ __forceinline__ void cpasync16(uint32_t dst, const void* src, int sz) {
    asm volatile("cp.async.cg.shared.global [%0], [%1], 16, %2;"
                 :: "r"(dst), "l"(src), "r"(sz) : "memory");
}
#define CP_COMMIT() asm volatile("cp.async.commit_group;" ::: "memory")
#define CP_WAIT(n)  asm volatile("cp.async.wait_group %0;" :: "n"(n) : "memory")
#define LDMX4(r, a) \
    asm volatile("ldmatrix.sync.aligned.m8n8.x4.shared.b16 {%0,%1,%2,%3}, [%4];" \
                 : "=r"((r)[0]), "=r"((r)[1]), "=r"((r)[2]), "=r"((r)[3]) : "r"(a))
__device__ __forceinline__ void mma16816(float* c, const uint32_t* a,
                                          uint32_t b0, uint32_t b1) {
    asm volatile(
        "mma.sync.aligned.m16n8k16.row.col.f32.bf16.bf16.f32 "
        "{%0,%1,%2,%3}, {%4,%5,%6,%7}, {%8,%9}, {%0,%1,%2,%3};"
        : "+f"(c[0]), "+f"(c[1]), "+f"(c[2]), "+f"(c[3])
        : "r"(a[0]), "r"(a[1]), "r"(a[2]), "r"(a[3]), "r"(b0), "r"(b1));
}
__device__ __forceinline__ void split1(float v, __nv_bfloat16& h, __nv_bfloat16& l) {
    h = __float2bfloat16_rn(v);
    l = __float2bfloat16_rn(v - __bfloat162float(h));
}

// ---------------- setup ----------------
__global__ void k_init() {
    int i = blockIdx.x * 256 + threadIdx.x;
    if (i < SLOT_CAP) g_slot_tok[i] = -1;
    if (i < NE) { g_cnt[i] = 0; g_fill[i] = 0; }
}

__global__ void k_gate(const float* __restrict__ x,
                       const float* __restrict__ Wg,
                       const float* __restrict__ bg) {
    int warp = (blockIdx.x * blockDim.x + threadIdx.x) >> 5;
    int lane = threadIdx.x & 31;
    if (warp >= BB) return;
    const float* xr = x + (size_t)warp * DIM;
    float acc[NE];
#pragma unroll
    for (int e = 0; e < NE; e++) acc[e] = 0.f;
    for (int d = lane; d < DIM; d += 32) {
        float xv = xr[d];
        const float4* w4 = reinterpret_cast<const float4*>(Wg + (size_t)d * NE);
        float4 a = w4[0], b = w4[1];
        acc[0] += xv * a.x; acc[1] += xv * a.y; acc[2] += xv * a.z; acc[3] += xv * a.w;
        acc[4] += xv * b.x; acc[5] += xv * b.y; acc[6] += xv * b.z; acc[7] += xv * b.w;
    }
#pragma unroll
    for (int e = 0; e < NE; e++) {
#pragma unroll
        for (int o = 16; o > 0; o >>= 1) acc[e] += __shfl_down_sync(0xffffffffu, acc[e], o);
    }
    if (lane == 0) {
        float z[NE], p[NE];
        float m = -1e30f;
#pragma unroll
        for (int e = 0; e < NE; e++) { z[e] = acc[e] + bg[e]; m = fmaxf(m, z[e]); }
        float s = 0.f;
#pragma unroll
        for (int e = 0; e < NE; e++) { p[e] = expf(z[e] - m); s += p[e]; }
        float inv = 1.f / s;
        int e0 = 0; float v0 = p[0];
#pragma unroll
        for (int e = 1; e < NE; e++) if (p[e] > v0) { v0 = p[e]; e0 = e; }
        int e1 = (e0 == 0) ? 1 : 0; float v1 = p[e1];
#pragma unroll
        for (int e = 0; e < NE; e++) if (e != e0 && p[e] > v1) { v1 = p[e]; e1 = e; }
        g_e0[warp] = e0; g_w0[warp] = v0 * inv;
        g_e1[warp] = e1; g_w1[warp] = v1 * inv;
        atomicAdd(&g_cnt[e0], 1);
        atomicAdd(&g_cnt[e1], 1);
    }
}

__global__ void k_offsets() {
    int o = 0;
    for (int e = 0; e < NE; e++) {
        g_off[e] = o;
        o += (g_cnt[e] + TM - 1) & ~(TM - 1);
    }
    g_off[NE] = o;
}

__global__ void k_scatter() {
    int b = blockIdx.x * blockDim.x + threadIdx.x;
    if (b >= BB) return;
    int e0 = g_e0[b];
    int s0 = g_off[e0] + atomicAdd(&g_fill[e0], 1);
    g_slot_tok[s0] = b;  g_s0[b] = s0;
    int e1 = g_e1[b];
    int s1 = g_off[e1] + atomicAdd(&g_fill[e1], 1);
    g_slot_tok[s1] = b;  g_s1[b] = s1;
}

// ---------------- prepass: split x,y elementwise ----------------
__global__ void k_split_xy(const float* __restrict__ x, const float* __restrict__ y) {
    size_t i = (size_t)blockIdx.x * 256 + threadIdx.x;
    if (i >= (size_t)BB * DIM) return;
    split1(x[i], g_xh[i], g_xl[i]);
    split1(y[i], g_yh[i], g_yl[i]);
}

// ---------------- prepass: transpose + split weights ----------------
// which=0: src = We (8 matrices R=2048 x C=6144) -> g_WeTh/l [e][n][k]
// which=1: src = Wp (R=2048 x C=2048)            -> g_WpTh/l [n][k]
__global__ void k_tsplit(const float* __restrict__ src, int C, int which) {
    __shared__ float tile[32][33];
    int c0 = blockIdx.x * 32, r0 = blockIdx.y * 32, e = blockIdx.z;
    int tx = threadIdx.x, ty = threadIdx.y;
    const float* s = src + (size_t)e * DIM * C;
#pragma unroll
    for (int i = ty; i < 32; i += 8)
        tile[i][tx] = s[(size_t)(r0 + i) * C + c0 + tx];
    __syncthreads();
    __nv_bfloat16* oh = which ? g_WpTh : (g_WeTh + (size_t)e * N3 * DIM);
    __nv_bfloat16* ol = which ? g_WpTl : (g_WeTl + (size_t)e * N3 * DIM);
#pragma unroll
    for (int i = ty; i < 32; i += 8) {
        float v = tile[tx][i];
        __nv_bfloat16 h, l;
        split1(v, h, l);
        size_t o = (size_t)(c0 + i) * DIM + r0 + tx;
        oh[o] = h;
        ol[o] = l;
    }
}

// ---------------- GEMM: cp.async pipelined, ldmatrix, 3-term bf16 ----------
// mode 0 (grid.x=48): x<32 -> kv path (A=x split, B=WeT n=2048+c), x>=32 -> q path
// mode 2 (grid.x=16): A=attn split, B=WpT, out=dout+bp
__global__ __launch_bounds__(256, 1)
void k_mm(const float* __restrict__ bp, float* __restrict__ dout, int mode)
{
    extern __shared__ char sm[];
    const int tid = threadIdx.x, wid = tid >> 5, lane = tid & 31;
    const int row0 = blockIdx.y * TM;

    const __nv_bfloat16 *Ah, *Al, *Bh, *Bl;
    bool gather;
    float* Cb; int ldc; int ccol0;
    if (mode == 2) {
        int col0 = blockIdx.x * TN;
        Ah = g_ah; Al = g_al;
        Bh = g_WpTh + (size_t)col0 * DIM;
        Bl = g_WpTl + (size_t)col0 * DIM;
        gather = false; Cb = dout; ldc = DIM; ccol0 = col0;
    } else {
        if (row0 >= g_off[NE]) return;
        int e = 0;
        while (e < NE - 1 && row0 >= g_off[e + 1]) e++;
        bool qpath = blockIdx.x >= 32;
        int col0 = (qpath ? blockIdx.x - 32 : blockIdx.x) * TN;
        int n0 = qpath ? col0 : (DIM + col0);
        Ah = qpath ? g_yh : g_xh;
        Al = qpath ? g_yl : g_xl;
        Bh = g_WeTh + ((size_t)e * N3 + n0) * DIM;
        Bl = g_WeTl + ((size_t)e * N3 + n0) * DIM;
        gather = true;
        Cb = qpath ? g_qs : g_kvs;
        ldc = qpath ? DIM : N2;
        ccol0 = col0;
    }

    int* sTok = (int*)sm;
    if (tid < TM) sTok[tid] = gather ? g_slot_tok[row0 + tid] : (row0 + tid);
    __syncthreads();
    const uint32_t sbU = s2u(sm);

    // per-thread load slots: q = tid*4+i ; row = q>>3, 16B-chunk col = q&7
    int lrow[4], lc8[4], ltok[4];
#pragma unroll
    for (int i = 0; i < 4; i++) {
        int q = tid * 4 + i;
        lrow[i] = q >> 3;
        lc8[i] = q & 7;
        int t = sTok[lrow[i]];
        ltok[i] = t;
    }

    // issue loads for chunk c into stage s
    auto load_chunk = [&](int c, int s) {
        const int k0 = c * KC;
        const uint32_t base = sbU + OFF_BUF + s * STAGE_B;
#pragma unroll
        for (int i = 0; i < 4; i++) {
            uint32_t dsw = SWZ((uint32_t)(lrow[i] * 128 + lc8[i] * 16));
            int tok = ltok[i];
            int ok = (tok >= 0) ? 16 : 0;
            size_t aoff = (size_t)(ok ? tok : 0) * DIM + k0 + lc8[i] * 8;
            cpasync16(base + dsw, Ah + aoff, ok);
            cpasync16(base + TILE_B + dsw, Al + aoff, ok);
            size_t boff = (size_t)lrow[i] * DIM + k0 + lc8[i] * 8;
            cpasync16(base + 2 * TILE_B + dsw, Bh + boff, 16);
            cpasync16(base + 3 * TILE_B + dsw, Bl + boff, 16);
        }
        CP_COMMIT();
    };

    const int warpRow = (wid & 1) * 64;
    const int warpCol = (wid >> 1) * 32;
    const int fr = lane & 15, fh = (lane >> 4) * 16;

    float acc[4][4][4];
#pragma unroll
    for (int i = 0; i < 4; i++)
#pragma unroll
        for (int j = 0; j < 4; j++)
#pragma unroll
            for (int t = 0; t < 4; t++) acc[i][j][t] = 0.f;

    load_chunk(0, 0);
    for (int c = 0; c < NCHUNK; c++) {
        const int st = c & 1;
        if (c + 1 < NCHUNK) {
            load_chunk(c + 1, st ^ 1);
            CP_WAIT(1);
        } else {
            CP_WAIT(0);
        }
        __syncthreads();
        const uint32_t base = sbU + OFF_BUF + st * STAGE_B;
#pragma unroll
        for (int s = 0; s < 4; s++) {
            const uint32_t kb = (uint32_t)(s * 32 + fh);
            uint32_t aH[4][4], aL[4][4], bH[2][4], bL[2][4];
#pragma unroll
            for (int i = 0; i < 4; i++) {
                uint32_t off = SWZ((uint32_t)((warpRow + 16 * i + fr) * 128) + kb);
                LDMX4(aH[i], base + off);
                LDMX4(aL[i], base + TILE_B + off);
            }
#pragma unroll
            for (int jj = 0; jj < 2; jj++) {
                uint32_t off = SWZ((uint32_t)((warpCol + 16 * jj + fr) * 128) + kb);
                LDMX4(bH[jj], base + 2 * TILE_B + off);
                LDMX4(bL[jj], base + 3 * TILE_B + off);
            }
#pragma unroll
            for (int i = 0; i < 4; i++)
#pragma unroll
                for (int j = 0; j < 4; j++) {
                    int jj = j >> 1, hs = j & 1;
                    mma16816(acc[i][j], aH[i], bH[jj][hs], bH[jj][hs + 2]);
                    mma16816(acc[i][j], aH[i], bL[jj][hs], bL[jj][hs + 2]);
                    mma16816(acc[i][j], aL[i], bH[jj][hs], bH[jj][hs + 2]);
                }
        }
        __syncthreads();
    }

    // epilogue (mapping validated in round 8)
    const int qrow = lane >> 2, klane = (lane & 3) * 2;
#pragma unroll
    for (int i = 0; i < 4; i++) {
        int r0 = row0 + warpRow + 16 * i + qrow;
#pragma unroll
        for (int j = 0; j < 4; j++) {
            int cc = ccol0 + warpCol + 8 * j + klane;
            float b0 = 0.f, b1 = 0.f;
            if (mode == 2) { b0 = bp[cc]; b1 = bp[cc + 1]; }
            *(float2*)(Cb + (size_t)r0 * ldc + cc) =
                make_float2(acc[i][j][0] + b0, acc[i][j][1] + b1);
            *(float2*)(Cb + (size_t)(r0 + 8) * ldc + cc) =
                make_float2(acc[i][j][2] + b0, acc[i][j][3] + b1);
        }
    }
}

// ---------------- per-token 16x16 head-attention; writes split bf16 --------
__global__ void k_attn() {
    int b = blockIdx.x;
    __shared__ float sQ[DIM], sK[DIM], sV[DIM];
    __shared__ float sS[NH][NH + 1];
    int tid = threadIdx.x;
    int s0 = g_s0[b], s1 = g_s1[b];
    float w0 = g_w0[b], w1 = g_w1[b];
    const float* q0 = g_qs + (size_t)s0 * DIM;
    const float* q1 = g_qs + (size_t)s1 * DIM;
    const float* kv0 = g_kvs + (size_t)s0 * N2;
    const float* kv1 = g_kvs + (size_t)s1 * N2;
    for (int i = tid; i < DIM; i += 256) {
        sQ[i] = w0 * q0[i] + w1 * q1[i];
        sK[i] = w0 * kv0[i] + w1 * kv1[i];
        sV[i] = w0 * kv0[DIM + i] + w1 * kv1[DIM + i];
    }
    __syncthreads();
    {
        int h = tid >> 4, g = tid & 15;
        float s = 0.f;
        int qb0 = h * HD, kb0 = g * HD;
#pragma unroll 8
        for (int dd = 0; dd < HD; dd++) {
            int d = (dd + tid) & (HD - 1);
            s += sQ[qb0 + d] * sK[kb0 + d];
        }
        sS[h][g] = s * SCALE_F;
    }
    __syncthreads();
    if (tid < NH) {
        float m = -1e30f;
#pragma unroll
        for (int g = 0; g < NH; g++) m = fmaxf(m, sS[tid][g]);
        float sum = 0.f;
#pragma unroll
        for (int g = 0; g < NH; g++) { float p = expf(sS[tid][g] - m); sS[tid][g] = p; sum += p; }
        float inv = 1.f / sum;
#pragma unroll
        for (int g = 0; g < NH; g++) sS[tid][g] *= inv;
    }
    __syncthreads();
    size_t ob = (size_t)b * DIM;
    for (int i = tid; i < DIM; i += 256) {
        int h = i >> 7, d = i & (HD - 1);
        float o = 0.f;
#pragma unroll
        for (int g = 0; g < NH; g++) o += sS[h][g] * sV[g * HD + d];
        __nv_bfloat16 hh, ll;
        split1(o, hh, ll);
        size_t idx = ob + (size_t)d * NH + h;   // swapaxes flatten
        g_ah[idx] = hh;
        g_al[idx] = ll;
    }
}

// ---------------- launch ----------------
extern "C" void kernel_launch(void* const* d_in, const int* in_sizes, int n_in,
                              void* d_out, int out_size) {
    const float *x = nullptr, *y = nullptr, *We = nullptr, *Wg = nullptr;
    const float *bg = nullptr, *Wp = nullptr, *bp = nullptr;
    for (int i = 0; i < n_in; i++) {
        const float* p = (const float*)d_in[i];
        switch (in_sizes[i]) {
            case 100663296: We = p; break;
            case 8388608:   if (!x) x = p; else y = p; break;
            case 4194304:   Wp = p; break;
            case 16384:     Wg = p; break;
            case 2048:      bp = p; break;
            case 8:         bg = p; break;
            default: break;
        }
    }
    float* out = (float*)d_out;

    cudaFuncSetAttribute(k_mm, cudaFuncAttributeMaxDynamicSharedMemorySize, SMEM_TOTAL);

    k_init<<<36, 256>>>();
    k_gate<<<BB / 8, 256>>>(x, Wg, bg);
    k_offsets<<<1, 1>>>();
    k_scatter<<<16, 256>>>();
    k_split_xy<<<(BB * DIM + 255) / 256, 256>>>(x, y);
    {
        dim3 grid(N3 / 32, DIM / 32, NE);
        dim3 blk(32, 8);
        k_tsplit<<<grid, blk>>>(We, N3, 0);
    }
    {
        dim3 grid(DIM / 32, DIM / 32, 1);
        dim3 blk(32, 8);
        k_tsplit<<<grid, blk>>>(Wp, DIM, 1);
    }
    {   // fused kv+q routed GEMMs
        dim3 grid(48, SLOT_TILES);
        k_mm<<<grid, 256, SMEM_TOTAL>>>(bp, out, 0);
    }
    k_attn<<<BB, 256>>>();
    {   // projection
        dim3 grid(DIM / TN, BB / TM);
        k_mm<<<grid, 256, SMEM_TOTAL>>>(bp, out, 2);
    }
}